// round 14
// baseline (speedup 1.0000x reference)
#include <cuda_runtime.h>
#include <cuda_fp16.h>
#include <cstdint>
#include <cstddef>

// ---------------------------------------------------------------------------
// Problem constants
// ---------------------------------------------------------------------------
#define BATCH 4
#define TSEQ  4096
#define EDIM  2048
#define DDIM  128
#define MTOT  (BATCH * TSEQ)   // 16384

// fp16 weights (pre-pass) and QKV outputs.
__device__ __half g_Wh[3 * EDIM * DDIM];    // 4.5 MB
__device__ __half g_Q [MTOT * DDIM];
__device__ __half g_K [MTOT * DDIM];
__device__ __half g_V [MTOT * DDIM];

// ---------------------------------------------------------------------------
// Helpers
// ---------------------------------------------------------------------------
__device__ __forceinline__ uint32_t smem_u32(const void* p) {
    uint32_t a;
    asm("{ .reg .u64 t; cvta.to.shared.u64 t, %1; cvt.u32.u64 %0, t; }"
        : "=r"(a) : "l"(p));
    return a;
}

__device__ __forceinline__ void cp_async16(uint32_t saddr, const void* gptr) {
    asm volatile("cp.async.cg.shared.global [%0], [%1], 16;"
                 :: "r"(saddr), "l"(gptr));
}
#define CP_COMMIT() asm volatile("cp.async.commit_group;" ::: "memory")
#define CP_WAIT(n)  asm volatile("cp.async.wait_group %0;" :: "n"(n) : "memory")

__device__ __forceinline__ float ex2f(float x) {
    float r;
    asm("ex2.approx.ftz.f32 %0, %1;" : "=f"(r) : "f"(x));
    return r;
}

__device__ __forceinline__ uint32_t packh2(float a, float b) {
    __half2 h = __floats2half2_rn(a, b);   // low = a, high = b
    return *(uint32_t*)&h;
}

// fp16 mma, fp32 accumulate: D(16x8) += A(16x16) * B(16x8)
__device__ __forceinline__ void mma_f16(float* d, const uint32_t* a, const uint32_t* b) {
    asm volatile(
        "mma.sync.aligned.m16n8k16.row.col.f32.f16.f16.f32 "
        "{%0,%1,%2,%3}, {%4,%5,%6,%7}, {%8,%9}, {%0,%1,%2,%3};\n"
        : "+f"(d[0]), "+f"(d[1]), "+f"(d[2]), "+f"(d[3])
        : "r"(a[0]), "r"(a[1]), "r"(a[2]), "r"(a[3]),
          "r"(b[0]), "r"(b[1]));
}

__device__ __forceinline__ void ldsm_x4(uint32_t& r0, uint32_t& r1,
                                        uint32_t& r2, uint32_t& r3, uint32_t a) {
    asm volatile("ldmatrix.sync.aligned.m8n8.x4.shared.b16 {%0,%1,%2,%3}, [%4];"
                 : "=r"(r0), "=r"(r1), "=r"(r2), "=r"(r3) : "r"(a));
}
__device__ __forceinline__ void ldsm_x4_t(uint32_t& r0, uint32_t& r1,
                                          uint32_t& r2, uint32_t& r3, uint32_t a) {
    asm volatile("ldmatrix.sync.aligned.m8n8.x4.trans.shared.b16 {%0,%1,%2,%3}, [%4];"
                 : "=r"(r0), "=r"(r1), "=r"(r2), "=r"(r3) : "r"(a));
}

// ---------------------------------------------------------------------------
// Kernel 0: fp32 -> fp16 conversion of the three W matrices only (~5 µs).
// ---------------------------------------------------------------------------
#define WBLK 384        // 384 * 256 * 8 = 786,432 = EDIM*DDIM

__global__ __launch_bounds__(256)
void cvt_w_kernel(const float* __restrict__ Wq,
                  const float* __restrict__ Wk,
                  const float* __restrict__ Wv)
{
    const int wz = blockIdx.x / WBLK;
    const float* src = (wz == 0) ? Wq : (wz == 1) ? Wk : Wv;
    __half* dst = g_Wh + (size_t)wz * EDIM * DDIM;
    size_t idx = ((size_t)(blockIdx.x % WBLK) * 256 + threadIdx.x) * 8;
    float4 v0 = *(const float4*)(src + idx);
    float4 v1 = *(const float4*)(src + idx + 4);
    uint4 u;
    u.x = packh2(v0.x, v0.y);
    u.y = packh2(v0.z, v0.w);
    u.z = packh2(v1.x, v1.y);
    u.w = packh2(v1.z, v1.w);
    *(uint4*)(dst + idx) = u;
}

// ---------------------------------------------------------------------------
// Kernel 1: QKV projection GEMM, fp16 mma.  R7 loop skeleton, but the A tile
//   is fp32 x staged via cp.async (latency-hidden, no register stage, no LDG
//   scoreboard stalls) and A fragments are built in-register via LDS.64+pack
//   using the m16n8k16 A-fragment mapping:
//     a0: row=lane>>2,  cols 2(lane&3), +1     a1: row+8, same cols
//     a2: row=lane>>2,  cols 2(lane&3)+8, +9   a3: row+8, same cols
//   B path / epilogue byte-identical to R7/R13 (proven).
// ---------------------------------------------------------------------------
#define GKC    64
#define ASTRF  68                        // fp32 words per A row (272 B)
#define HBSTR  136                       // halves per B row (272 B)
#define ABYTES (128 * ASTRF * 4)         // 34816 per stage
#define BBYTES (GKC * HBSTR * 2)         // 17408 per stage
#define GEMM_SMEM (2 * ABYTES + 2 * BBYTES)   // 104448 bytes

__global__ __launch_bounds__(256, 2)
void qkv_mma_kernel(const float* __restrict__ x)
{
    extern __shared__ char smg[];
    const uint32_t as_b = smem_u32(smg);
    const uint32_t bs_b = as_b + 2 * ABYTES;
    float* Af = (float*)smg;             // [2][128][ASTRF]

    const int z = blockIdx.x;
    const __half* W = g_Wh + (size_t)z * EDIM * DDIM;
    __half* Y       = (z == 0) ? g_Q : (z == 1) ? g_K : g_V;
    const int row0 = blockIdx.y * 128;

    const int tid  = threadIdx.x;
    const int lane = tid & 31;
    const int wid  = tid >> 5;
    const int wm   = wid >> 1;    // 0..3 (32 rows)
    const int wn   = wid & 1;     // 0..1 (64 cols)

    float acc[2][8][4];
    #pragma unroll
    for (int mt = 0; mt < 2; mt++)
        #pragma unroll
        for (int nt = 0; nt < 8; nt++)
            #pragma unroll
            for (int q = 0; q < 4; q++)
                acc[mt][nt][q] = 0.0f;

    auto issue = [&](int c, int buf) {
        const int k0 = c * GKC;
        // A: x fp32, 128 rows x 16 float4-chunks = 2048, 8/thread (coalesced:
        // 16 lanes per row -> 2 full 128B lines per warp-LDG... via cp.async).
        #pragma unroll
        for (int t = 0; t < 8; t++) {
            int e = tid + t * 256;
            int r = e >> 4, c4 = e & 15;
            cp_async16(as_b + (uint32_t)buf * ABYTES
                            + (uint32_t)(r * ASTRF + c4 * 4) * 4,
                       x + (size_t)(row0 + r) * EDIM + k0 + c4 * 4);
        }
        // B: g_Wh fp16, 64 rows x 16 chunks of 8 halves = 1024, 4/thread.
        #pragma unroll
        for (int t = 0; t < 4; t++) {
            int e = tid + t * 256;
            int r = e >> 4, c8 = e & 15;
            cp_async16(bs_b + (uint32_t)buf * BBYTES
                            + (uint32_t)(r * HBSTR + c8 * 8) * 2,
                       W + (size_t)(k0 + r) * DDIM + c8 * 8);
        }
    };

    issue(0, 0);
    CP_COMMIT();

    // A-fragment lane coordinates (m16n8k16 layout)
    const int fr = lane >> 2;           // 0..7
    const int fc = 2 * (lane & 3);      // 0,2,4,6
    // B ldmatrix lane-address components
    const uint32_t brow = (uint32_t)((lane & 7) + (((lane >> 3) & 1) << 3));
    const uint32_t bcol = (uint32_t)((lane >> 4) << 3);

    const int NCH = EDIM / GKC;   // 32
    for (int c = 0; c < NCH; c++) {
        if (c < NCH - 1) { issue(c + 1, (c + 1) & 1); CP_COMMIT(); CP_WAIT(1); }
        else             { CP_WAIT(0); }
        __syncthreads();

        const float* Asb = Af + (size_t)(c & 1) * (128 * ASTRF);
        const uint32_t bsb = bs_b + (uint32_t)(c & 1) * BBYTES;

        #pragma unroll
        for (int ks = 0; ks < GKC / 16; ks++) {       // 4 k16-steps
            // Build A fragments in-register from fp32 smem (warp-local rows).
            uint32_t a[2][4];
            #pragma unroll
            for (int mt = 0; mt < 2; mt++) {
                const int rbase = wm * 32 + mt * 16 + fr;
                const int cb    = ks * 16 + fc;
                float2 v0 = *(const float2*)(Asb + rbase * ASTRF + cb);
                float2 v1 = *(const float2*)(Asb + (rbase + 8) * ASTRF + cb);
                float2 v2 = *(const float2*)(Asb + rbase * ASTRF + cb + 8);
                float2 v3 = *(const float2*)(Asb + (rbase + 8) * ASTRF + cb + 8);
                a[mt][0] = packh2(v0.x, v0.y);
                a[mt][1] = packh2(v1.x, v1.y);
                a[mt][2] = packh2(v2.x, v2.y);
                a[mt][3] = packh2(v3.x, v3.y);
            }
            #pragma unroll
            for (int p = 0; p < 4; p++) {             // 4 n16-pairs -> n=64
                uint32_t b0, b1, b2, b3;
                ldsm_x4_t(b0, b1, b2, b3,
                          bsb + (uint32_t)((ks * 16 + brow) * HBSTR
                                           + wn * 64 + p * 16 + bcol) * 2);
                uint32_t bl[2] = {b0, b1};
                uint32_t bh[2] = {b2, b3};
                #pragma unroll
                for (int mt = 0; mt < 2; mt++) {
                    mma_f16(acc[mt][2 * p],     a[mt], bl);
                    mma_f16(acc[mt][2 * p + 1], a[mt], bh);
                }
            }
        }
        __syncthreads();
    }

    // Epilogue: fp16 stores; Q pre-scaled by log2(e)/sqrt(D).
    const float sc = (z == 0) ? 0.1275413575339156f : 1.0f;
    #pragma unroll
    for (int mt = 0; mt < 2; mt++) {
        const int r0 = row0 + wm * 32 + mt * 16 + (lane >> 2);
        #pragma unroll
        for (int nt = 0; nt < 8; nt++) {
            const int col = wn * 64 + nt * 8 + 2 * (lane & 3);
            *(uint32_t*)(Y + (size_t)r0 * DDIM + col) =
                packh2(acc[mt][nt][0] * sc, acc[mt][nt][1] * sc);
            *(uint32_t*)(Y + (size_t)(r0 + 8) * DDIM + col) =
                packh2(acc[mt][nt][2] * sc, acc[mt][nt][3] * sc);
        }
    }
}

// ---------------------------------------------------------------------------
// Kernel 2: causal flash attention, fp16 mma + ldmatrix.
//   Byte-identical to R13 (passed: ~106 µs, rel_err 6.09e-4).
// ---------------------------------------------------------------------------
#define BQ     64
#define BKV    64
#define QSTRH  136
#define KSTRH  136
#define PSTRH  72
#define QBYTES (BQ * QSTRH * 2)
#define KBYTES (BKV * KSTRH * 2)
#define PBYTES (BQ * PSTRH * 2)
#define ATT_SMEM (QBYTES + 4 * KBYTES + PBYTES)   // 96256 bytes

__global__ __launch_bounds__(128, 2)
void attn_mma_kernel(float* __restrict__ out)
{
    extern __shared__ char smc[];
    const uint32_t qs_b = smem_u32(smc);
    const uint32_t kb_b = qs_b + QBYTES;
    const uint32_t vb_b = kb_b + 2 * KBYTES;
    const uint32_t ps_b = vb_b + 2 * KBYTES;

    const int bid  = blockIdx.x;
    const int rank = (bid < 148) ? bid : (403 - bid);
    const int qi   = 63 - (rank >> 2);
    const int b    = rank & 3;

    const int tid  = threadIdx.x;
    const int lane = tid & 31;
    const int wid  = tid >> 5;

    const __half* Qg = g_Q + ((size_t)b * TSEQ + (size_t)qi * BQ) * DDIM;
    const __half* Kg = g_K + (size_t)b * TSEQ * DDIM;
    const __half* Vg = g_V + (size_t)b * TSEQ * DDIM;

    #pragma unroll
    for (int t = 0; t < 8; t++) {
        int e = tid + t * 128;
        int r = e >> 4, c16 = e & 15;
        cp_async16(qs_b + (uint32_t)(r * QSTRH + c16 * 8) * 2,
                   Qg + (size_t)r * DDIM + c16 * 8);
    }
    CP_COMMIT();

    auto issue_kv = [&](int j, int buf) {
        const __half* kg = Kg + (size_t)j * BKV * DDIM;
        const __half* vg = Vg + (size_t)j * BKV * DDIM;
        const uint32_t kd = kb_b + (uint32_t)buf * KBYTES;
        const uint32_t vd = vb_b + (uint32_t)buf * KBYTES;
        #pragma unroll
        for (int t = 0; t < 8; t++) {
            int e = tid + t * 128;
            int r = e >> 4, c16 = e & 15;
            uint32_t off = (uint32_t)(r * KSTRH + c16 * 8) * 2;
            cp_async16(kd + off, kg + (size_t)r * DDIM + c16 * 8);
            cp_async16(vd + off, vg + (size_t)r * DDIM + c16 * 8);
        }
    };

    issue_kv(0, 0);
    CP_COMMIT();

    CP_WAIT(1);      // Q group complete
    __syncthreads();
    uint32_t qf[8][4];
    {
        const uint32_t base = qs_b +
            (uint32_t)((wid * 16 + (lane & 15)) * QSTRH + (lane >> 4) * 8) * 2;
        #pragma unroll
        for (int ks = 0; ks < 8; ks++)
            ldsm_x4(qf[ks][0], qf[ks][1], qf[ks][2], qf[ks][3],
                    base + (uint32_t)(ks * 16) * 2);
    }

    float m0 = -1e30f, m1 = -1e30f, l0 = 0.0f, l1 = 0.0f;
    float o[16][4];
    #pragma unroll
    for (int nt = 0; nt < 16; nt++)
        #pragma unroll
        for (int q = 0; q < 4; q++)
            o[nt][q] = 0.0f;

    const int jmax = qi;
    for (int j = 0; j <= jmax; j++) {
        if (j < jmax) { issue_kv(j + 1, (j + 1) & 1); CP_COMMIT(); CP_WAIT(1); }
        else          { CP_WAIT(0); }
        __syncthreads();

        const uint32_t ksb = kb_b + (uint32_t)(j & 1) * KBYTES;
        const uint32_t vsb = vb_b + (uint32_t)(j & 1) * KBYTES;

        const bool active = (j * BKV <= qi * BQ + wid * 16 + 15);
        if (active) {
            float s[8][4];
            #pragma unroll
            for (int nt = 0; nt < 8; nt++)
                #pragma unroll
                for (int q = 0; q < 4; q++)
                    s[nt][q] = 0.0f;

            const uint32_t krow = (uint32_t)((lane & 7) + ((lane >> 4) << 3));
            const uint32_t kcol = (uint32_t)(((lane >> 3) & 1) << 3);
            #pragma unroll
            for (int ks = 0; ks < 8; ks++) {
                #pragma unroll
                for (int p = 0; p < 4; p++) {
                    uint32_t b0, b1, b2, b3;
                    ldsm_x4(b0, b1, b2, b3,
                            ksb + (uint32_t)((p * 16 + krow) * KSTRH + ks * 16 + kcol) * 2);
                    uint32_t bl[2] = {b0, b1};
                    uint32_t bh[2] = {b2, b3};
                    mma_f16(s[2 * p],     qf[ks], bl);
                    mma_f16(s[2 * p + 1], qf[ks], bh);
                }
            }

            if (j * BKV + BKV - 1 > qi * BQ + wid * 16) {
                const int grow = qi * BQ + wid * 16 + (lane >> 2);
                #pragma unroll
                for (int nt = 0; nt < 8; nt++) {
                    const int gc = j * BKV + nt * 8 + 2 * (lane & 3);
                    if (gc     > grow)     s[nt][0] = -1e30f;
                    if (gc + 1 > grow)     s[nt][1] = -1e30f;
                    if (gc     > grow + 8) s[nt][2] = -1e30f;
                    if (gc + 1 > grow + 8) s[nt][3] = -1e30f;
                }
            }

            float mx0 = -1e30f, mx1 = -1e30f;
            #pragma unroll
            for (int nt = 0; nt < 8; nt++) {
                mx0 = fmaxf(mx0, fmaxf(s[nt][0], s[nt][1]));
                mx1 = fmaxf(mx1, fmaxf(s[nt][2], s[nt][3]));
            }
            mx0 = fmaxf(mx0, __shfl_xor_sync(0xffffffffu, mx0, 1));
            mx0 = fmaxf(mx0, __shfl_xor_sync(0xffffffffu, mx0, 2));
            mx1 = fmaxf(mx1, __shfl_xor_sync(0xffffffffu, mx1, 1));
            mx1 = fmaxf(mx1, __shfl_xor_sync(0xffffffffu, mx1, 2));

            const float mn0 = fmaxf(m0, mx0);
            const float mn1 = fmaxf(m1, mx1);
            const float f0 = ex2f(m0 - mn0);
            const float f1 = ex2f(m1 - mn1);

            float sum0 = 0.0f, sum1 = 0.0f;
            #pragma unroll
            for (int nt = 0; nt < 8; nt++) {
                s[nt][0] = ex2f(s[nt][0] - mn0);
                s[nt][1] = ex2f(s[nt][1] - mn0);
                s[nt][2] = ex2f(s[nt][2] - mn1);
                s[nt][3] = ex2f(s[nt][3] - mn1);
                sum0 += s[nt][0] + s[nt][1];
                sum1 += s[nt][2] + s[nt][3];
            }
            sum0 += __shfl_xor_sync(0xffffffffu, sum0, 1);
            sum0 += __shfl_xor_sync(0xffffffffu, sum0, 2);
            sum1 += __shfl_xor_sync(0xffffffffu, sum1, 1);
            sum1 += __shfl_xor_sync(0xffffffffu, sum1, 2);

            l0 = l0 * f0 + sum0;  m0 = mn0;
            l1 = l1 * f1 + sum1;  m1 = mn1;

            // Exact rescale-skip: ex2(0)==1.0 and x*1.0f is an identity.
            if (__any_sync(0xffffffffu, (f0 != 1.0f) || (f1 != 1.0f))) {
                #pragma unroll
                for (int nt = 0; nt < 16; nt++) {
                    o[nt][0] *= f0; o[nt][1] *= f0;
                    o[nt][2] *= f1; o[nt][3] *= f1;
                }
            }

            {
                const int pr = wid * 16 + (lane >> 2);
                const int pc = 2 * (lane & 3);
                #pragma unroll
                for (int nt = 0; nt < 8; nt++) {
                    *(uint32_t*)(smc + (ps_b - qs_b) +
                        (uint32_t)(pr * PSTRH + nt * 8 + pc) * 2) =
                        packh2(s[nt][0], s[nt][1]);
                    *(uint32_t*)(smc + (ps_b - qs_b) +
                        (uint32_t)((pr + 8) * PSTRH + nt * 8 + pc) * 2) =
                        packh2(s[nt][2], s[nt][3]);
                }
            }
            __syncwarp();

            const uint32_t pbase = ps_b +
                (uint32_t)((wid * 16 + (lane & 15)) * PSTRH + (lane >> 4) * 8) * 2;
            const uint32_t vrow = (uint32_t)((lane & 7) + (((lane >> 3) & 1) << 3));
            const uint32_t vcol = (uint32_t)((lane >> 4) << 3);
            #pragma unroll
            for (int kc = 0; kc < 4; kc++) {
                uint32_t a[4];
                ldsm_x4(a[0], a[1], a[2], a[3], pbase + (uint32_t)(kc * 16) * 2);
                #pragma unroll
                for (int p = 0; p < 8; p++) {
                    uint32_t b0, b1, b2, b3;
                    ldsm_x4_t(b0, b1, b2, b3,
                              vsb + (uint32_t)((kc * 16 + vrow) * KSTRH + p * 16 + vcol) * 2);
                    uint32_t bl[2] = {b0, b1};
                    uint32_t bh[2] = {b2, b3};
                    mma_f16(o[2 * p],     a, bl);
                    mma_f16(o[2 * p + 1], a, bh);
                }
            }
        }
        __syncthreads();   // BOTTOM barrier: protects stage (j+2)&1 overwrite
    }

    const float inv0 = 1.0f / l0;
    const float inv1 = 1.0f / l1;
    const int rg = qi * BQ + wid * 16 + (lane >> 2);
    float* Og = out + (size_t)b * TSEQ * DDIM;
    #pragma unroll
    for (int nt = 0; nt < 16; nt++) {
        const int col = nt * 8 + 2 * (lane & 3);
        float2 lo = make_float2(o[nt][0] * inv0, o[nt][1] * inv0);
        float2 hi = make_float2(o[nt][2] * inv1, o[nt][3] * inv1);
        *(float2*)(Og + (size_t)rg * DDIM + col)       = lo;
        *(float2*)(Og + (size_t)(rg + 8) * DDIM + col) = hi;
    }
}

// ---------------------------------------------------------------------------
// Launch
// ---------------------------------------------------------------------------
extern "C" void kernel_launch(void* const* d_in, const int* in_sizes, int n_in,
                              void* d_out, int out_size)
{
    (void)in_sizes; (void)n_in; (void)out_size;
    const float* x  = (const float*)d_in[0];
    const float* Wq = (const float*)d_in[1];
    const float* Wk = (const float*)d_in[2];
    const float* Wv = (const float*)d_in[3];
    float* out = (float*)d_out;

    cvt_w_kernel<<<3 * WBLK, 256>>>(Wq, Wk, Wv);

    cudaFuncSetAttribute(qkv_mma_kernel,
                         cudaFuncAttributeMaxDynamicSharedMemorySize, GEMM_SMEM);
    dim3 g1(3, MTOT / 128);
    qkv_mma_kernel<<<g1, 256, GEMM_SMEM>>>(x);

    cudaFuncSetAttribute(attn_mma_kernel,
                         cudaFuncAttributeMaxDynamicSharedMemorySize, ATT_SMEM);
    attn_mma_kernel<<<(TSEQ / BQ) * BATCH, 128, ATT_SMEM>>>(out);
}

// round 15
// speedup vs baseline: 1.0688x; 1.0688x over previous
#include <cuda_runtime.h>
#include <cuda_fp16.h>
#include <cstdint>
#include <cstddef>

// ---------------------------------------------------------------------------
// Problem constants
// ---------------------------------------------------------------------------
#define BATCH 4
#define TSEQ  4096
#define EDIM  2048
#define DDIM  128
#define MTOT  (BATCH * TSEQ)   // 16384

// fp16 copies of inputs (pre-pass) and QKV outputs.
__device__ __half g_X [MTOT * EDIM];        // 64 MB
__device__ __half g_Wh[3 * EDIM * DDIM];    // 4.5 MB
__device__ __half g_Q [MTOT * DDIM];
__device__ __half g_K [MTOT * DDIM];
__device__ __half g_V [MTOT * DDIM];

// ---------------------------------------------------------------------------
// Helpers
// ---------------------------------------------------------------------------
__device__ __forceinline__ uint32_t smem_u32(const void* p) {
    uint32_t a;
    asm("{ .reg .u64 t; cvta.to.shared.u64 t, %1; cvt.u32.u64 %0, t; }"
        : "=r"(a) : "l"(p));
    return a;
}

__device__ __forceinline__ void cp_async16(uint32_t saddr, const void* gptr) {
    asm volatile("cp.async.cg.shared.global [%0], [%1], 16;"
                 :: "r"(saddr), "l"(gptr));
}
#define CP_COMMIT() asm volatile("cp.async.commit_group;" ::: "memory")
#define CP_WAIT(n)  asm volatile("cp.async.wait_group %0;" :: "n"(n) : "memory")

__device__ __forceinline__ float ex2f(float x) {
    float r;
    asm("ex2.approx.ftz.f32 %0, %1;" : "=f"(r) : "f"(x));
    return r;
}

// Packed fp16 exp2: two exponentials in one MUFU op.
__device__ __forceinline__ uint32_t h2ex2(uint32_t x) {
    uint32_t r;
    asm("ex2.approx.f16x2 %0, %1;" : "=r"(r) : "r"(x));
    return r;
}

__device__ __forceinline__ uint32_t packh2(float a, float b) {
    __half2 h = __floats2half2_rn(a, b);   // low = a, high = b
    return *(uint32_t*)&h;
}

__device__ __forceinline__ float2 h2f2(uint32_t p) {
    __half2 h = *(__half2*)&p;
    return __half22float2(h);
}

// fp16 mma, fp32 accumulate: D(16x8) += A(16x16) * B(16x8)
__device__ __forceinline__ void mma_f16(float* d, const uint32_t* a, const uint32_t* b) {
    asm volatile(
        "mma.sync.aligned.m16n8k16.row.col.f32.f16.f16.f32 "
        "{%0,%1,%2,%3}, {%4,%5,%6,%7}, {%8,%9}, {%0,%1,%2,%3};\n"
        : "+f"(d[0]), "+f"(d[1]), "+f"(d[2]), "+f"(d[3])
        : "r"(a[0]), "r"(a[1]), "r"(a[2]), "r"(a[3]),
          "r"(b[0]), "r"(b[1]));
}

__device__ __forceinline__ void ldsm_x4(uint32_t& r0, uint32_t& r1,
                                        uint32_t& r2, uint32_t& r3, uint32_t a) {
    asm volatile("ldmatrix.sync.aligned.m8n8.x4.shared.b16 {%0,%1,%2,%3}, [%4];"
                 : "=r"(r0), "=r"(r1), "=r"(r2), "=r"(r3) : "r"(a));
}
__device__ __forceinline__ void ldsm_x4_t(uint32_t& r0, uint32_t& r1,
                                          uint32_t& r2, uint32_t& r3, uint32_t a) {
    asm volatile("ldmatrix.sync.aligned.m8n8.x4.trans.shared.b16 {%0,%1,%2,%3}, [%4];"
                 : "=r"(r0), "=r"(r1), "=r"(r2), "=r"(r3) : "r"(a));
}

// ---------------------------------------------------------------------------
// Kernel 0: fp32 -> fp16 conversion pre-pass (x and the three W matrices).
//   (proven: ~28.5 µs, 77-79% DRAM)
// ---------------------------------------------------------------------------
#define XBLK 16384      // 16384 * 256 * 8 = 33,554,432 = MTOT*EDIM
#define WBLK 384        //   384 * 256 * 8 =    786,432 = EDIM*DDIM

__global__ __launch_bounds__(256)
void cvt_fp16_kernel(const float* __restrict__ x,
                     const float* __restrict__ Wq,
                     const float* __restrict__ Wk,
                     const float* __restrict__ Wv)
{
    const int bx = blockIdx.x;
    const float* src;
    __half* dst;
    size_t idx;
    if (bx < XBLK) {
        src = x; dst = g_X;
        idx = ((size_t)bx * 256 + threadIdx.x) * 8;
    } else {
        const int wz = (bx - XBLK) / WBLK;
        src = (wz == 0) ? Wq : (wz == 1) ? Wk : Wv;
        dst = g_Wh + (size_t)wz * EDIM * DDIM;
        idx = ((size_t)((bx - XBLK) % WBLK) * 256 + threadIdx.x) * 8;
    }
    float4 v0 = *(const float4*)(src + idx);
    float4 v1 = *(const float4*)(src + idx + 4);
    uint4 u;
    u.x = packh2(v0.x, v0.y);
    u.y = packh2(v0.z, v0.w);
    u.z = packh2(v1.x, v1.y);
    u.w = packh2(v1.z, v1.w);
    *(uint4*)(dst + idx) = u;
}

// ---------------------------------------------------------------------------
// Kernel 1: QKV projection GEMM, fp16 mma + ldmatrix.  (proven ~62 µs)
//   Byte-identical to R7/R13.
// ---------------------------------------------------------------------------
#define GKC    64
#define HASTR  72                        // halves per A row (144 B)
#define HBSTR  136                       // halves per B row (272 B)
#define ABYTES (128 * HASTR * 2)         // 18432 per stage
#define BBYTES (GKC * HBSTR * 2)         // 17408 per stage
#define GEMM_SMEM (2 * ABYTES + 2 * BBYTES)   // 71680 bytes

__global__ __launch_bounds__(256, 2)
void qkv_mma_kernel()
{
    extern __shared__ char smg[];
    const uint32_t as_b = smem_u32(smg);
    const uint32_t bs_b = as_b + 2 * ABYTES;

    const int z = blockIdx.x;
    const __half* W = g_Wh + (size_t)z * EDIM * DDIM;
    __half* Y       = (z == 0) ? g_Q : (z == 1) ? g_K : g_V;
    const int row0 = blockIdx.y * 128;

    const int tid  = threadIdx.x;
    const int lane = tid & 31;
    const int wid  = tid >> 5;
    const int wm   = wid >> 1;    // 0..3
    const int wn   = wid & 1;     // 0..1

    float acc[2][8][4];
    #pragma unroll
    for (int mt = 0; mt < 2; mt++)
        #pragma unroll
        for (int nt = 0; nt < 8; nt++)
            #pragma unroll
            for (int q = 0; q < 4; q++)
                acc[mt][nt][q] = 0.0f;

    auto issue = [&](int c, int buf) {
        const int k0 = c * GKC;
        #pragma unroll
        for (int t = 0; t < 4; t++) {
            int e = tid + t * 256;
            int r = e >> 3, c8 = e & 7;
            cp_async16(as_b + (uint32_t)buf * ABYTES + (uint32_t)(r * HASTR + c8 * 8) * 2,
                       g_X + (size_t)(row0 + r) * EDIM + k0 + c8 * 8);
        }
        #pragma unroll
        for (int t = 0; t < 4; t++) {
            int e = tid + t * 256;
            int r = e >> 4, c8 = e & 15;
            cp_async16(bs_b + (uint32_t)buf * BBYTES + (uint32_t)(r * HBSTR + c8 * 8) * 2,
                       W + (size_t)(k0 + r) * DDIM + c8 * 8);
        }
    };

    issue(0, 0);
    CP_COMMIT();

    const uint32_t arow = (uint32_t)(lane & 15);
    const uint32_t acol = (uint32_t)((lane >> 4) << 3);
    const uint32_t brow = (uint32_t)((lane & 7) + (((lane >> 3) & 1) << 3));
    const uint32_t bcol = (uint32_t)((lane >> 4) << 3);

    const int NCH = EDIM / GKC;   // 32
    for (int c = 0; c < NCH; c++) {
        if (c < NCH - 1) { issue(c + 1, (c + 1) & 1); CP_COMMIT(); CP_WAIT(1); }
        else             { CP_WAIT(0); }
        __syncthreads();

        const uint32_t asb = as_b + (uint32_t)(c & 1) * ABYTES;
        const uint32_t bsb = bs_b + (uint32_t)(c & 1) * BBYTES;

        #pragma unroll
        for (int ks = 0; ks < GKC / 16; ks++) {
            uint32_t a[2][4];
            #pragma unroll
            for (int mt = 0; mt < 2; mt++)
                ldsm_x4(a[mt][0], a[mt][1], a[mt][2], a[mt][3],
                        asb + (uint32_t)((wm * 32 + mt * 16 + arow) * HASTR
                                         + ks * 16 + acol) * 2);
            #pragma unroll
            for (int p = 0; p < 4; p++) {
                uint32_t b0, b1, b2, b3;
                ldsm_x4_t(b0, b1, b2, b3,
                          bsb + (uint32_t)((ks * 16 + brow) * HBSTR
                                           + wn * 64 + p * 16 + bcol) * 2);
                uint32_t bl[2] = {b0, b1};
                uint32_t bh[2] = {b2, b3};
                #pragma unroll
                for (int mt = 0; mt < 2; mt++) {
                    mma_f16(acc[mt][2 * p],     a[mt], bl);
                    mma_f16(acc[mt][2 * p + 1], a[mt], bh);
                }
            }
        }
        __syncthreads();
    }

    const float sc = (z == 0) ? 0.1275413575339156f : 1.0f;   // log2e/sqrt(128)
    #pragma unroll
    for (int mt = 0; mt < 2; mt++) {
        const int r0 = row0 + wm * 32 + mt * 16 + (lane >> 2);
        #pragma unroll
        for (int nt = 0; nt < 8; nt++) {
            const int col = wn * 64 + nt * 8 + 2 * (lane & 3);
            *(uint32_t*)(Y + (size_t)r0 * DDIM + col) =
                packh2(acc[mt][nt][0] * sc, acc[mt][nt][1] * sc);
            *(uint32_t*)(Y + (size_t)(r0 + 8) * DDIM + col) =
                packh2(acc[mt][nt][2] * sc, acc[mt][nt][3] * sc);
        }
    }
}

// ---------------------------------------------------------------------------
// Kernel 2: causal flash attention, fp16 mma + ldmatrix.
//   R13 structure; softmax exp now in packed fp16 (ex2.approx.f16x2):
//   half the MUFU ops, and results double as the staged P values. l is the
//   sum of exactly the fp16 P used in PV (self-consistent normalization).
// ---------------------------------------------------------------------------
#define BQ     64
#define BKV    64
#define QSTRH  136
#define KSTRH  136
#define PSTRH  72
#define QBYTES (BQ * QSTRH * 2)
#define KBYTES (BKV * KSTRH * 2)
#define PBYTES (BQ * PSTRH * 2)
#define ATT_SMEM (QBYTES + 4 * KBYTES + PBYTES)   // 96256 bytes

__global__ __launch_bounds__(128, 2)
void attn_mma_kernel(float* __restrict__ out)
{
    extern __shared__ char smc[];
    const uint32_t qs_b = smem_u32(smc);
    const uint32_t kb_b = qs_b + QBYTES;
    const uint32_t vb_b = kb_b + 2 * KBYTES;
    const uint32_t ps_b = vb_b + 2 * KBYTES;

    const int bid  = blockIdx.x;
    const int rank = (bid < 148) ? bid : (403 - bid);
    const int qi   = 63 - (rank >> 2);
    const int b    = rank & 3;

    const int tid  = threadIdx.x;
    const int lane = tid & 31;
    const int wid  = tid >> 5;

    const __half* Qg = g_Q + ((size_t)b * TSEQ + (size_t)qi * BQ) * DDIM;
    const __half* Kg = g_K + (size_t)b * TSEQ * DDIM;
    const __half* Vg = g_V + (size_t)b * TSEQ * DDIM;

    #pragma unroll
    for (int t = 0; t < 8; t++) {
        int e = tid + t * 128;
        int r = e >> 4, c16 = e & 15;
        cp_async16(qs_b + (uint32_t)(r * QSTRH + c16 * 8) * 2,
                   Qg + (size_t)r * DDIM + c16 * 8);
    }
    CP_COMMIT();

    auto issue_kv = [&](int j, int buf) {
        const __half* kg = Kg + (size_t)j * BKV * DDIM;
        const __half* vg = Vg + (size_t)j * BKV * DDIM;
        const uint32_t kd = kb_b + (uint32_t)buf * KBYTES;
        const uint32_t vd = vb_b + (uint32_t)buf * KBYTES;
        #pragma unroll
        for (int t = 0; t < 8; t++) {
            int e = tid + t * 128;
            int r = e >> 4, c16 = e & 15;
            uint32_t off = (uint32_t)(r * KSTRH + c16 * 8) * 2;
            cp_async16(kd + off, kg + (size_t)r * DDIM + c16 * 8);
            cp_async16(vd + off, vg + (size_t)r * DDIM + c16 * 8);
        }
    };

    issue_kv(0, 0);
    CP_COMMIT();

    CP_WAIT(1);      // Q group complete
    __syncthreads();
    uint32_t qf[8][4];
    {
        const uint32_t base = qs_b +
            (uint32_t)((wid * 16 + (lane & 15)) * QSTRH + (lane >> 4) * 8) * 2;
        #pragma unroll
        for (int ks = 0; ks < 8; ks++)
            ldsm_x4(qf[ks][0], qf[ks][1], qf[ks][2], qf[ks][3],
                    base + (uint32_t)(ks * 16) * 2);
    }

    float m0 = -1e30f, m1 = -1e30f, l0 = 0.0f, l1 = 0.0f;
    float o[16][4];
    #pragma unroll
    for (int nt = 0; nt < 16; nt++)
        #pragma unroll
        for (int q = 0; q < 4; q++)
            o[nt][q] = 0.0f;

    const int jmax = qi;
    for (int j = 0; j <= jmax; j++) {
        if (j < jmax) { issue_kv(j + 1, (j + 1) & 1); CP_COMMIT(); CP_WAIT(1); }
        else          { CP_WAIT(0); }
        __syncthreads();

        const uint32_t ksb = kb_b + (uint32_t)(j & 1) * KBYTES;
        const uint32_t vsb = vb_b + (uint32_t)(j & 1) * KBYTES;

        const bool active = (j * BKV <= qi * BQ + wid * 16 + 15);
        if (active) {
            float s[8][4];
            #pragma unroll
            for (int nt = 0; nt < 8; nt++)
                #pragma unroll
                for (int q = 0; q < 4; q++)
                    s[nt][q] = 0.0f;

            const uint32_t krow = (uint32_t)((lane & 7) + ((lane >> 4) << 3));
            const uint32_t kcol = (uint32_t)(((lane >> 3) & 1) << 3);
            #pragma unroll
            for (int ks = 0; ks < 8; ks++) {
                #pragma unroll
                for (int p = 0; p < 4; p++) {
                    uint32_t b0, b1, b2, b3;
                    ldsm_x4(b0, b1, b2, b3,
                            ksb + (uint32_t)((p * 16 + krow) * KSTRH + ks * 16 + kcol) * 2);
                    uint32_t bl[2] = {b0, b1};
                    uint32_t bh[2] = {b2, b3};
                    mma_f16(s[2 * p],     qf[ks], bl);
                    mma_f16(s[2 * p + 1], qf[ks], bh);
                }
            }

            if (j * BKV + BKV - 1 > qi * BQ + wid * 16) {
                const int grow = qi * BQ + wid * 16 + (lane >> 2);
                #pragma unroll
                for (int nt = 0; nt < 8; nt++) {
                    const int gc = j * BKV + nt * 8 + 2 * (lane & 3);
                    if (gc     > grow)     s[nt][0] = -1e30f;
                    if (gc + 1 > grow)     s[nt][1] = -1e30f;
                    if (gc     > grow + 8) s[nt][2] = -1e30f;
                    if (gc + 1 > grow + 8) s[nt][3] = -1e30f;
                }
            }

            float mx0 = -1e30f, mx1 = -1e30f;
            #pragma unroll
            for (int nt = 0; nt < 8; nt++) {
                mx0 = fmaxf(mx0, fmaxf(s[nt][0], s[nt][1]));
                mx1 = fmaxf(mx1, fmaxf(s[nt][2], s[nt][3]));
            }
            mx0 = fmaxf(mx0, __shfl_xor_sync(0xffffffffu, mx0, 1));
            mx0 = fmaxf(mx0, __shfl_xor_sync(0xffffffffu, mx0, 2));
            mx1 = fmaxf(mx1, __shfl_xor_sync(0xffffffffu, mx1, 1));
            mx1 = fmaxf(mx1, __shfl_xor_sync(0xffffffffu, mx1, 2));

            const float mn0 = fmaxf(m0, mx0);
            const float mn1 = fmaxf(m1, mx1);
            const float f0 = ex2f(m0 - mn0);
            const float f1 = ex2f(m1 - mn1);

            // Packed fp16 exp: ph[2nt] = exp2(s[nt][0..1]-mn0) (row r),
            //                  ph[2nt+1] = exp2(s[nt][2..3]-mn1) (row r+8).
            // These are exactly the fp16 P values consumed by the PV mma,
            // and l sums exactly these values (self-consistent softmax).
            uint32_t ph[16];
            float sum0 = 0.0f, sum1 = 0.0f;
            #pragma unroll
            for (int nt = 0; nt < 8; nt++) {
                ph[2 * nt]     = h2ex2(packh2(s[nt][0] - mn0, s[nt][1] - mn0));
                ph[2 * nt + 1] = h2ex2(packh2(s[nt][2] - mn1, s[nt][3] - mn1));
                float2 e0 = h2f2(ph[2 * nt]);
                float2 e1 = h2f2(ph[2 * nt + 1]);
                sum0 += e0.x + e0.y;
                sum1 += e1.x + e1.y;
            }
            sum0 += __shfl_xor_sync(0xffffffffu, sum0, 1);
            sum0 += __shfl_xor_sync(0xffffffffu, sum0, 2);
            sum1 += __shfl_xor_sync(0xffffffffu, sum1, 1);
            sum1 += __shfl_xor_sync(0xffffffffu, sum1, 2);

            l0 = l0 * f0 + sum0;  m0 = mn0;
            l1 = l1 * f1 + sum1;  m1 = mn1;

            // Exact rescale-skip: ex2(0)==1.0 and x*1.0f is an identity.
            if (__any_sync(0xffffffffu, (f0 != 1.0f) || (f1 != 1.0f))) {
                #pragma unroll
                for (int nt = 0; nt < 16; nt++) {
                    o[nt][0] *= f0; o[nt][1] *= f0;
                    o[nt][2] *= f1; o[nt][3] *= f1;
                }
            }

            // Stage P: the packed exp results ARE the fp16 P values.
            {
                const int pr = wid * 16 + (lane >> 2);
                const int pc = 2 * (lane & 3);
                #pragma unroll
                for (int nt = 0; nt < 8; nt++) {
                    *(uint32_t*)(smc + (ps_b - qs_b) +
                        (uint32_t)(pr * PSTRH + nt * 8 + pc) * 2) = ph[2 * nt];
                    *(uint32_t*)(smc + (ps_b - qs_b) +
                        (uint32_t)((pr + 8) * PSTRH + nt * 8 + pc) * 2) = ph[2 * nt + 1];
                }
            }
            __syncwarp();

            const uint32_t pbase = ps_b +
                (uint32_t)((wid * 16 + (lane & 15)) * PSTRH + (lane >> 4) * 8) * 2;
            const uint32_t vrow = (uint32_t)((lane & 7) + (((lane >> 3) & 1) << 3));
            const uint32_t vcol = (uint32_t)((lane >> 4) << 3);
            #pragma unroll
            for (int kc = 0; kc < 4; kc++) {
                uint32_t a[4];
                ldsm_x4(a[0], a[1], a[2], a[3], pbase + (uint32_t)(kc * 16) * 2);
                #pragma unroll
                for (int p = 0; p < 8; p++) {
                    uint32_t b0, b1, b2, b3;
                    ldsm_x4_t(b0, b1, b2, b3,
                              vsb + (uint32_t)((kc * 16 + vrow) * KSTRH + p * 16 + vcol) * 2);
                    uint32_t bl[2] = {b0, b1};
                    uint32_t bh[2] = {b2, b3};
                    mma_f16(o[2 * p],     a, bl);
                    mma_f16(o[2 * p + 1], a, bh);
                }
            }
        }
        __syncthreads();   // BOTTOM barrier: protects stage (j+2)&1 overwrite
    }

    const float inv0 = 1.0f / l0;
    const float inv1 = 1.0f / l1;
    const int rg = qi * BQ + wid * 16 + (lane >> 2);
    float* Og = out + (size_t)b * TSEQ * DDIM;
    #pragma unroll
    for (int nt = 0; nt < 16; nt++) {
        const int col = nt * 8 + 2 * (lane & 3);
        float2 lo = make_float2(o[nt][0] * inv0, o[nt][1] * inv0);
        float2 hi = make_float2(o[nt][2] * inv1, o[nt][3] * inv1);
        *(float2*)(Og + (size_t)rg * DDIM + col)       = lo;
        *(float2*)(Og + (size_t)(rg + 8) * DDIM + col) = hi;
    }
}

// ---------------------------------------------------------------------------
// Launch
// ---------------------------------------------------------------------------
extern "C" void kernel_launch(void* const* d_in, const int* in_sizes, int n_in,
                              void* d_out, int out_size)
{
    (void)in_sizes; (void)n_in; (void)out_size;
    const float* x  = (const float*)d_in[0];
    const float* Wq = (const float*)d_in[1];
    const float* Wk = (const float*)d_in[2];
    const float* Wv = (const float*)d_in[3];
    float* out = (float*)d_out;

    cvt_fp16_kernel<<<XBLK + 3 * WBLK, 256>>>(x, Wq, Wk, Wv);

    cudaFuncSetAttribute(qkv_mma_kernel,
                         cudaFuncAttributeMaxDynamicSharedMemorySize, GEMM_SMEM);
    dim3 g1(3, MTOT / 128);
    qkv_mma_kernel<<<g1, 256, GEMM_SMEM>>>();

    cudaFuncSetAttribute(attn_mma_kernel,
                         cudaFuncAttributeMaxDynamicSharedMemorySize, ATT_SMEM);
    attn_mma_kernel<<<(TSEQ / BQ) * BATCH, 128, ATT_SMEM>>>(out);
}

// round 16
// speedup vs baseline: 1.0872x; 1.0172x over previous
#include <cuda_runtime.h>
#include <cuda_fp16.h>
#include <cstdint>
#include <cstddef>

// ---------------------------------------------------------------------------
// Problem constants
// ---------------------------------------------------------------------------
#define BATCH 4
#define TSEQ  4096
#define EDIM  2048
#define DDIM  128
#define MTOT  (BATCH * TSEQ)   // 16384

// fp16 copies of inputs (pre-pass) and QKV outputs.
__device__ __half g_X [MTOT * EDIM];        // 64 MB
__device__ __half g_Wh[3 * EDIM * DDIM];    // 4.5 MB
__device__ __half g_Q [MTOT * DDIM];
__device__ __half g_K [MTOT * DDIM];
__device__ __half g_V [MTOT * DDIM];

// ---------------------------------------------------------------------------
// Helpers
// ---------------------------------------------------------------------------
__device__ __forceinline__ uint32_t smem_u32(const void* p) {
    uint32_t a;
    asm("{ .reg .u64 t; cvta.to.shared.u64 t, %1; cvt.u32.u64 %0, t; }"
        : "=r"(a) : "l"(p));
    return a;
}

__device__ __forceinline__ void cp_async16(uint32_t saddr, const void* gptr) {
    asm volatile("cp.async.cg.shared.global [%0], [%1], 16;"
                 :: "r"(saddr), "l"(gptr));
}
#define CP_COMMIT() asm volatile("cp.async.commit_group;" ::: "memory")
#define CP_WAIT(n)  asm volatile("cp.async.wait_group %0;" :: "n"(n) : "memory")

__device__ __forceinline__ float ex2f(float x) {
    float r;
    asm("ex2.approx.ftz.f32 %0, %1;" : "=f"(r) : "f"(x));
    return r;
}

__device__ __forceinline__ uint32_t packh2(float a, float b) {
    __half2 h = __floats2half2_rn(a, b);   // low = a, high = b
    return *(uint32_t*)&h;
}

// fp16 mma, fp32 accumulate: D(16x8) += A(16x16) * B(16x8)
__device__ __forceinline__ void mma_f16(float* d, const uint32_t* a, const uint32_t* b) {
    asm volatile(
        "mma.sync.aligned.m16n8k16.row.col.f32.f16.f16.f32 "
        "{%0,%1,%2,%3}, {%4,%5,%6,%7}, {%8,%9}, {%0,%1,%2,%3};\n"
        : "+f"(d[0]), "+f"(d[1]), "+f"(d[2]), "+f"(d[3])
        : "r"(a[0]), "r"(a[1]), "r"(a[2]), "r"(a[3]),
          "r"(b[0]), "r"(b[1]));
}

__device__ __forceinline__ void ldsm_x4(uint32_t& r0, uint32_t& r1,
                                        uint32_t& r2, uint32_t& r3, uint32_t a) {
    asm volatile("ldmatrix.sync.aligned.m8n8.x4.shared.b16 {%0,%1,%2,%3}, [%4];"
                 : "=r"(r0), "=r"(r1), "=r"(r2), "=r"(r3) : "r"(a));
}
__device__ __forceinline__ void ldsm_x4_t(uint32_t& r0, uint32_t& r1,
                                          uint32_t& r2, uint32_t& r3, uint32_t a) {
    asm volatile("ldmatrix.sync.aligned.m8n8.x4.trans.shared.b16 {%0,%1,%2,%3}, [%4];"
                 : "=r"(r0), "=r"(r1), "=r"(r2), "=r"(r3) : "r"(a));
}

// ---------------------------------------------------------------------------
// Kernel 0: fp32 -> fp16 conversion pre-pass (x and the three W matrices).
//   (proven: ~28.5 µs, 77-79% DRAM)
// ---------------------------------------------------------------------------
#define XBLK 16384      // 16384 * 256 * 8 = 33,554,432 = MTOT*EDIM
#define WBLK 384        //   384 * 256 * 8 =    786,432 = EDIM*DDIM

__global__ __launch_bounds__(256)
void cvt_fp16_kernel(const float* __restrict__ x,
                     const float* __restrict__ Wq,
                     const float* __restrict__ Wk,
                     const float* __restrict__ Wv)
{
    const int bx = blockIdx.x;
    const float* src;
    __half* dst;
    size_t idx;
    if (bx < XBLK) {
        src = x; dst = g_X;
        idx = ((size_t)bx * 256 + threadIdx.x) * 8;
    } else {
        const int wz = (bx - XBLK) / WBLK;
        src = (wz == 0) ? Wq : (wz == 1) ? Wk : Wv;
        dst = g_Wh + (size_t)wz * EDIM * DDIM;
        idx = ((size_t)((bx - XBLK) % WBLK) * 256 + threadIdx.x) * 8;
    }
    float4 v0 = *(const float4*)(src + idx);
    float4 v1 = *(const float4*)(src + idx + 4);
    uint4 u;
    u.x = packh2(v0.x, v0.y);
    u.y = packh2(v0.z, v0.w);
    u.z = packh2(v1.x, v1.y);
    u.w = packh2(v1.z, v1.w);
    *(uint4*)(dst + idx) = u;
}

// ---------------------------------------------------------------------------
// Kernel 1: QKV projection GEMM, fp16 mma + ldmatrix.
//   3-stage cp.async pipeline, ONE barrier per iteration:
//     iter c: WAIT(1) (last iter: WAIT(0)) -> barrier
//             -> issue(c+2) into stage (c+2)%3 -> body on stage c%3
//   Safety: stage (c+2)%3 == (c-1)%3; its readers (body c-1) finished before
//   every warp reached barrier c (body c-1 precedes WAIT+barrier in program
//   order), and the issue is post-barrier. Publication of stage c: every
//   thread issued part of group c and waited on it before barrier c (the
//   R7-proven pattern). FIFO group completion makes WAIT(1) => group c done.
// ---------------------------------------------------------------------------
#define GKC    64
#define HASTR  72                        // halves per A row (144 B)
#define HBSTR  136                       // halves per B row (272 B)
#define ABYTES (128 * HASTR * 2)         // 18432 per stage
#define BBYTES (GKC * HBSTR * 2)         // 17408 per stage
#define NSTG   3
#define GEMM_SMEM (NSTG * (ABYTES + BBYTES))   // 107520 bytes

__global__ __launch_bounds__(256, 2)
void qkv_mma_kernel()
{
    extern __shared__ char smg[];
    const uint32_t as_b = smem_u32(smg);
    const uint32_t bs_b = as_b + NSTG * ABYTES;

    const int z = blockIdx.x;
    const __half* W = g_Wh + (size_t)z * EDIM * DDIM;
    __half* Y       = (z == 0) ? g_Q : (z == 1) ? g_K : g_V;
    const int row0 = blockIdx.y * 128;

    const int tid  = threadIdx.x;
    const int lane = tid & 31;
    const int wid  = tid >> 5;
    const int wm   = wid >> 1;    // 0..3
    const int wn   = wid & 1;     // 0..1

    float acc[2][8][4];
    #pragma unroll
    for (int mt = 0; mt < 2; mt++)
        #pragma unroll
        for (int nt = 0; nt < 8; nt++)
            #pragma unroll
            for (int q = 0; q < 4; q++)
                acc[mt][nt][q] = 0.0f;

    auto issue = [&](int c, int buf) {
        const int k0 = c * GKC;
        // A: 128 rows x 8 chunks of 8 halves
        #pragma unroll
        for (int t = 0; t < 4; t++) {
            int e = tid + t * 256;
            int r = e >> 3, c8 = e & 7;
            cp_async16(as_b + (uint32_t)buf * ABYTES + (uint32_t)(r * HASTR + c8 * 8) * 2,
                       g_X + (size_t)(row0 + r) * EDIM + k0 + c8 * 8);
        }
        // B: 64 rows x 16 chunks of 8 halves
        #pragma unroll
        for (int t = 0; t < 4; t++) {
            int e = tid + t * 256;
            int r = e >> 4, c8 = e & 15;
            cp_async16(bs_b + (uint32_t)buf * BBYTES + (uint32_t)(r * HBSTR + c8 * 8) * 2,
                       W + (size_t)(k0 + r) * DDIM + c8 * 8);
        }
    };

    // Prologue: groups 0 and 1 in flight.
    issue(0, 0);
    CP_COMMIT();
    issue(1, 1);
    CP_COMMIT();

    // ldmatrix lane-address components
    const uint32_t arow = (uint32_t)(lane & 15);
    const uint32_t acol = (uint32_t)((lane >> 4) << 3);
    const uint32_t brow = (uint32_t)((lane & 7) + (((lane >> 3) & 1) << 3));
    const uint32_t bcol = (uint32_t)((lane >> 4) << 3);

    const int NCH = EDIM / GKC;   // 32
    int sc = 0;                   // c % 3
    for (int c = 0; c < NCH; c++) {
        if (c < NCH - 1) CP_WAIT(1);
        else             CP_WAIT(0);
        __syncthreads();          // group c visible to all; body c-1 done by all

        if (c + 2 < NCH) {
            int s2 = sc + 2; if (s2 >= 3) s2 -= 3;     // (c+2)%3
            issue(c + 2, s2);
            CP_COMMIT();
        }

        const uint32_t asb = as_b + (uint32_t)sc * ABYTES;
        const uint32_t bsb = bs_b + (uint32_t)sc * BBYTES;

        #pragma unroll
        for (int ks = 0; ks < GKC / 16; ks++) {       // 4 k16-steps
            uint32_t a[2][4];
            #pragma unroll
            for (int mt = 0; mt < 2; mt++)
                ldsm_x4(a[mt][0], a[mt][1], a[mt][2], a[mt][3],
                        asb + (uint32_t)((wm * 32 + mt * 16 + arow) * HASTR
                                         + ks * 16 + acol) * 2);
            #pragma unroll
            for (int p = 0; p < 4; p++) {             // 4 n16-pairs -> n=64
                uint32_t b0, b1, b2, b3;
                ldsm_x4_t(b0, b1, b2, b3,
                          bsb + (uint32_t)((ks * 16 + brow) * HBSTR
                                           + wn * 64 + p * 16 + bcol) * 2);
                uint32_t bl[2] = {b0, b1};
                uint32_t bh[2] = {b2, b3};
                #pragma unroll
                for (int mt = 0; mt < 2; mt++) {
                    mma_f16(acc[mt][2 * p],     a[mt], bl);
                    mma_f16(acc[mt][2 * p + 1], a[mt], bh);
                }
            }
        }
        if (++sc == 3) sc = 0;
    }

    // Epilogue: fp16 stores; Q pre-scaled by log2(e)/sqrt(D).
    const float sc2 = (z == 0) ? 0.1275413575339156f : 1.0f;
    #pragma unroll
    for (int mt = 0; mt < 2; mt++) {
        const int r0 = row0 + wm * 32 + mt * 16 + (lane >> 2);
        #pragma unroll
        for (int nt = 0; nt < 8; nt++) {
            const int col = wn * 64 + nt * 8 + 2 * (lane & 3);
            *(uint32_t*)(Y + (size_t)r0 * DDIM + col) =
                packh2(acc[mt][nt][0] * sc2, acc[mt][nt][1] * sc2);
            *(uint32_t*)(Y + (size_t)(r0 + 8) * DDIM + col) =
                packh2(acc[mt][nt][2] * sc2, acc[mt][nt][3] * sc2);
        }
    }
}

// ---------------------------------------------------------------------------
// Kernel 2: causal flash attention, fp16 mma + ldmatrix.
//   Byte-identical to R13 (passed at 203.3: ~106 µs, rel_err 6.089e-4).
// ---------------------------------------------------------------------------
#define BQ     64
#define BKV    64
#define QSTRH  136
#define KSTRH  136
#define PSTRH  72
#define QBYTES (BQ * QSTRH * 2)
#define KBYTES (BKV * KSTRH * 2)
#define PBYTES (BQ * PSTRH * 2)
#define ATT_SMEM (QBYTES + 4 * KBYTES + PBYTES)   // 96256 bytes

__global__ __launch_bounds__(128, 2)
void attn_mma_kernel(float* __restrict__ out)
{
    extern __shared__ char smc[];
    const uint32_t qs_b = smem_u32(smc);
    const uint32_t kb_b = qs_b + QBYTES;
    const uint32_t vb_b = kb_b + 2 * KBYTES;
    const uint32_t ps_b = vb_b + 2 * KBYTES;

    const int bid  = blockIdx.x;
    const int rank = (bid < 148) ? bid : (403 - bid);
    const int qi   = 63 - (rank >> 2);
    const int b    = rank & 3;

    const int tid  = threadIdx.x;
    const int lane = tid & 31;
    const int wid  = tid >> 5;

    const __half* Qg = g_Q + ((size_t)b * TSEQ + (size_t)qi * BQ) * DDIM;
    const __half* Kg = g_K + (size_t)b * TSEQ * DDIM;
    const __half* Vg = g_V + (size_t)b * TSEQ * DDIM;

    #pragma unroll
    for (int t = 0; t < 8; t++) {
        int e = tid + t * 128;
        int r = e >> 4, c16 = e & 15;
        cp_async16(qs_b + (uint32_t)(r * QSTRH + c16 * 8) * 2,
                   Qg + (size_t)r * DDIM + c16 * 8);
    }
    CP_COMMIT();

    auto issue_kv = [&](int j, int buf) {
        const __half* kg = Kg + (size_t)j * BKV * DDIM;
        const __half* vg = Vg + (size_t)j * BKV * DDIM;
        const uint32_t kd = kb_b + (uint32_t)buf * KBYTES;
        const uint32_t vd = vb_b + (uint32_t)buf * KBYTES;
        #pragma unroll
        for (int t = 0; t < 8; t++) {
            int e = tid + t * 128;
            int r = e >> 4, c16 = e & 15;
            uint32_t off = (uint32_t)(r * KSTRH + c16 * 8) * 2;
            cp_async16(kd + off, kg + (size_t)r * DDIM + c16 * 8);
            cp_async16(vd + off, vg + (size_t)r * DDIM + c16 * 8);
        }
    };

    issue_kv(0, 0);
    CP_COMMIT();

    CP_WAIT(1);      // Q group complete
    __syncthreads();
    uint32_t qf[8][4];
    {
        const uint32_t base = qs_b +
            (uint32_t)((wid * 16 + (lane & 15)) * QSTRH + (lane >> 4) * 8) * 2;
        #pragma unroll
        for (int ks = 0; ks < 8; ks++)
            ldsm_x4(qf[ks][0], qf[ks][1], qf[ks][2], qf[ks][3],
                    base + (uint32_t)(ks * 16) * 2);
    }

    float m0 = -1e30f, m1 = -1e30f, l0 = 0.0f, l1 = 0.0f;
    float o[16][4];
    #pragma unroll
    for (int nt = 0; nt < 16; nt++)
        #pragma unroll
        for (int q = 0; q < 4; q++)
            o[nt][q] = 0.0f;

    const int jmax = qi;
    for (int j = 0; j <= jmax; j++) {
        if (j < jmax) { issue_kv(j + 1, (j + 1) & 1); CP_COMMIT(); CP_WAIT(1); }
        else          { CP_WAIT(0); }
        __syncthreads();

        const uint32_t ksb = kb_b + (uint32_t)(j & 1) * KBYTES;
        const uint32_t vsb = vb_b + (uint32_t)(j & 1) * KBYTES;

        const bool active = (j * BKV <= qi * BQ + wid * 16 + 15);
        if (active) {
            float s[8][4];
            #pragma unroll
            for (int nt = 0; nt < 8; nt++)
                #pragma unroll
                for (int q = 0; q < 4; q++)
                    s[nt][q] = 0.0f;

            const uint32_t krow = (uint32_t)((lane & 7) + ((lane >> 4) << 3));
            const uint32_t kcol = (uint32_t)(((lane >> 3) & 1) << 3);
            #pragma unroll
            for (int ks = 0; ks < 8; ks++) {
                #pragma unroll
                for (int p = 0; p < 4; p++) {
                    uint32_t b0, b1, b2, b3;
                    ldsm_x4(b0, b1, b2, b3,
                            ksb + (uint32_t)((p * 16 + krow) * KSTRH + ks * 16 + kcol) * 2);
                    uint32_t bl[2] = {b0, b1};
                    uint32_t bh[2] = {b2, b3};
                    mma_f16(s[2 * p],     qf[ks], bl);
                    mma_f16(s[2 * p + 1], qf[ks], bh);
                }
            }

            if (j * BKV + BKV - 1 > qi * BQ + wid * 16) {
                const int grow = qi * BQ + wid * 16 + (lane >> 2);
                #pragma unroll
                for (int nt = 0; nt < 8; nt++) {
                    const int gc = j * BKV + nt * 8 + 2 * (lane & 3);
                    if (gc     > grow)     s[nt][0] = -1e30f;
                    if (gc + 1 > grow)     s[nt][1] = -1e30f;
                    if (gc     > grow + 8) s[nt][2] = -1e30f;
                    if (gc + 1 > grow + 8) s[nt][3] = -1e30f;
                }
            }

            float mx0 = -1e30f, mx1 = -1e30f;
            #pragma unroll
            for (int nt = 0; nt < 8; nt++) {
                mx0 = fmaxf(mx0, fmaxf(s[nt][0], s[nt][1]));
                mx1 = fmaxf(mx1, fmaxf(s[nt][2], s[nt][3]));
            }
            mx0 = fmaxf(mx0, __shfl_xor_sync(0xffffffffu, mx0, 1));
            mx0 = fmaxf(mx0, __shfl_xor_sync(0xffffffffu, mx0, 2));
            mx1 = fmaxf(mx1, __shfl_xor_sync(0xffffffffu, mx1, 1));
            mx1 = fmaxf(mx1, __shfl_xor_sync(0xffffffffu, mx1, 2));

            const float mn0 = fmaxf(m0, mx0);
            const float mn1 = fmaxf(m1, mx1);
            const float f0 = ex2f(m0 - mn0);
            const float f1 = ex2f(m1 - mn1);

            float sum0 = 0.0f, sum1 = 0.0f;
            #pragma unroll
            for (int nt = 0; nt < 8; nt++) {
                s[nt][0] = ex2f(s[nt][0] - mn0);
                s[nt][1] = ex2f(s[nt][1] - mn0);
                s[nt][2] = ex2f(s[nt][2] - mn1);
                s[nt][3] = ex2f(s[nt][3] - mn1);
                sum0 += s[nt][0] + s[nt][1];
                sum1 += s[nt][2] + s[nt][3];
            }
            sum0 += __shfl_xor_sync(0xffffffffu, sum0, 1);
            sum0 += __shfl_xor_sync(0xffffffffu, sum0, 2);
            sum1 += __shfl_xor_sync(0xffffffffu, sum1, 1);
            sum1 += __shfl_xor_sync(0xffffffffu, sum1, 2);

            l0 = l0 * f0 + sum0;  m0 = mn0;
            l1 = l1 * f1 + sum1;  m1 = mn1;

            // Exact rescale-skip: ex2(0)==1.0 and x*1.0f is an identity.
            if (__any_sync(0xffffffffu, (f0 != 1.0f) || (f1 != 1.0f))) {
                #pragma unroll
                for (int nt = 0; nt < 16; nt++) {
                    o[nt][0] *= f0; o[nt][1] *= f0;
                    o[nt][2] *= f1; o[nt][3] *= f1;
                }
            }

            {
                const int pr = wid * 16 + (lane >> 2);
                const int pc = 2 * (lane & 3);
                #pragma unroll
                for (int nt = 0; nt < 8; nt++) {
                    *(uint32_t*)(smc + (ps_b - qs_b) +
                        (uint32_t)(pr * PSTRH + nt * 8 + pc) * 2) =
                        packh2(s[nt][0], s[nt][1]);
                    *(uint32_t*)(smc + (ps_b - qs_b) +
                        (uint32_t)((pr + 8) * PSTRH + nt * 8 + pc) * 2) =
                        packh2(s[nt][2], s[nt][3]);
                }
            }
            __syncwarp();

            const uint32_t pbase = ps_b +
                (uint32_t)((wid * 16 + (lane & 15)) * PSTRH + (lane >> 4) * 8) * 2;
            const uint32_t vrow = (uint32_t)((lane & 7) + (((lane >> 3) & 1) << 3));
            const uint32_t vcol = (uint32_t)((lane >> 4) << 3);
            #pragma unroll
            for (int kc = 0; kc < 4; kc++) {
                uint32_t a[4];
                ldsm_x4(a[0], a[1], a[2], a[3], pbase + (uint32_t)(kc * 16) * 2);
                #pragma unroll
                for (int p = 0; p < 8; p++) {
                    uint32_t b0, b1, b2, b3;
                    ldsm_x4_t(b0, b1, b2, b3,
                              vsb + (uint32_t)((kc * 16 + vrow) * KSTRH + p * 16 + vcol) * 2);
                    uint32_t bl[2] = {b0, b1};
                    uint32_t bh[2] = {b2, b3};
                    mma_f16(o[2 * p],     a, bl);
                    mma_f16(o[2 * p + 1], a, bh);
                }
            }
        }
        __syncthreads();   // BOTTOM barrier: protects stage (j+2)&1 overwrite
    }

    const float inv0 = 1.0f / l0;
    const float inv1 = 1.0f / l1;
    const int rg = qi * BQ + wid * 16 + (lane >> 2);
    float* Og = out + (size_t)b * TSEQ * DDIM;
    #pragma unroll
    for (int nt = 0; nt < 16; nt++) {
        const int col = nt * 8 + 2 * (lane & 3);
        float2 lo = make_float2(o[nt][0] * inv0, o[nt][1] * inv0);
        float2 hi = make_float2(o[nt][2] * inv1, o[nt][3] * inv1);
        *(float2*)(Og + (size_t)rg * DDIM + col)       = lo;
        *(float2*)(Og + (size_t)(rg + 8) * DDIM + col) = hi;
    }
}

// ---------------------------------------------------------------------------
// Launch
// ---------------------------------------------------------------------------
extern "C" void kernel_launch(void* const* d_in, const int* in_sizes, int n_in,
                              void* d_out, int out_size)
{
    (void)in_sizes; (void)n_in; (void)out_size;
    const float* x  = (const float*)d_in[0];
    const float* Wq = (const float*)d_in[1];
    const float* Wk = (const float*)d_in[2];
    const float* Wv = (const float*)d_in[3];
    float* out = (float*)d_out;

    cvt_fp16_kernel<<<XBLK + 3 * WBLK, 256>>>(x, Wq, Wk, Wv);

    cudaFuncSetAttribute(qkv_mma_kernel,
                         cudaFuncAttributeMaxDynamicSharedMemorySize, GEMM_SMEM);
    dim3 g1(3, MTOT / 128);
    qkv_mma_kernel<<<g1, 256, GEMM_SMEM>>>();

    cudaFuncSetAttribute(attn_mma_kernel,
                         cudaFuncAttributeMaxDynamicSharedMemorySize, ATT_SMEM);
    attn_mma_kernel<<<(TSEQ / BQ) * BATCH, 128, ATT_SMEM>>>(out);
}